// round 1
// baseline (speedup 1.0000x reference)
#include <cuda_runtime.h>
#include <cstdint>

// NetNew_17162689315115: 8-layer op-net, B=524288 rows.
// One thread per row; h[80] register-resident; weights staged to shared
// (rows padded to multiple of 4 floats for LDS.128 broadcast).

#define NUM_LAYERS 8

// Per-layer input dims and padded dims (pad rows to multiple of 4).
// DIN[L]  = 8 + 9*L
// DPAD[L] = round_up(DIN[L], 4)
// OFF[L]  = prefix sum of 13*DPAD
__device__ __constant__ const int c_dummy = 0; // (nothing needed; all constexpr below)

struct NetParams {
    const float* W[9];   // W1..W8, Wf
    const float* x;
    float*       out;
    int          B;
};

template <int L> struct LayerCfg {
    static constexpr int DIN  = 8 + 9 * L;
    static constexpr int DPAD = (DIN + 3) & ~3;
    static constexpr int BASE = 72 - 9 * L;       // start of current h in buffer
};

// offsets (floats) of each layer's padded weight block in shared
template <int L> struct WOff;
template <> struct WOff<0> { static constexpr int V = 0; };
template <int L> struct WOff {
    static constexpr int V = WOff<L - 1>::V + 13 * LayerCfg<L - 1>::DPAD;
};
static constexpr int WF_OFF   = WOff<7>::V + 13 * LayerCfg<7>::DPAD; // 4264
static constexpr int SM_FLOATS = WF_OFF + 80;                        // 4344

__device__ __forceinline__ float clip_mag(float v, float mx) {
    // matches jnp.where(|v| >= mx, v * |mx/v|, v) including inf -> NaN edge case
    if (fabsf(v) >= mx) v = v * fabsf(mx / v);
    return v;
}

template <int L>
__device__ __forceinline__ void do_layer(float* __restrict__ h,
                                         const float* __restrict__ smw) {
    constexpr int DP   = LayerCfg<L>::DPAD;
    constexpr int BASE = LayerCfg<L>::BASE;
    const float* wl = smw + WOff<L>::V;

    float z[13];
#pragma unroll
    for (int j = 0; j < 13; ++j) {
        float acc = 0.0f;
#pragma unroll
        for (int k = 0; k < DP; k += 4) {
            float4 w = *reinterpret_cast<const float4*>(wl + j * DP + k);
            acc = fmaf(w.x, h[BASE + k + 0], acc);
            acc = fmaf(w.y, h[BASE + k + 1], acc);
            acc = fmaf(w.z, h[BASE + k + 2], acc);
            acc = fmaf(w.w, h[BASE + k + 3], acc);
        }
        z[j] = acc;
    }

    float* o = h + (BASE - 9);
    // '+'
    o[0] = z[0] + z[1];
    // '-'
    o[1] = z[2] - z[3];
    // '*'  clip at 99999999
    o[2] = clip_mag(z[4] * z[5], 99999999.0f);
    // '/'  denom fix at exactly 0, clip at 9999
    {
        float b   = z[7];
        float den = (b == 0.0f) ? (b + 0.0001f) : b;
        o[3] = clip_mag(z[6] / den, 9999.0f);
    }
    // sin / cos (precise libdevice paths, matches XLA lowering)
    o[4] = sinf(z[8]);
    o[5] = cosf(z[9]);
    // exp with upper clamp at 17: a >= 17 -> a * (17/a)
    {
        float a = z[10];
        if (a >= 17.0f) a = a * (17.0f / a);
        o[6] = expf(a);
    }
    // log(|a|)
    o[7] = logf(fabsf(z[11]));
    // square, clip at 99999999
    o[8] = clip_mag(z[12] * z[12], 99999999.0f);
}

__global__ __launch_bounds__(256)
void netnew_kernel(NetParams p) {
    __shared__ __align__(16) float smw[SM_FLOATS];

    // ---- stage weights into shared (padded rows, zero fill) ----
    {
        // unrolled per-layer copy; divisions are by compile-time constants
#define STAGE_LAYER(L)                                                        \
        {                                                                     \
            constexpr int D  = LayerCfg<L>::DIN;                              \
            constexpr int DP = LayerCfg<L>::DPAD;                             \
            const float* g = p.W[L];                                          \
            for (int i = threadIdx.x; i < 13 * DP; i += blockDim.x) {         \
                int r = i / DP, c = i - r * DP;                               \
                smw[WOff<L>::V + i] = (c < D) ? g[r * D + c] : 0.0f;          \
            }                                                                 \
        }
        STAGE_LAYER(0) STAGE_LAYER(1) STAGE_LAYER(2) STAGE_LAYER(3)
        STAGE_LAYER(4) STAGE_LAYER(5) STAGE_LAYER(6) STAGE_LAYER(7)
#undef STAGE_LAYER
        for (int i = threadIdx.x; i < 80; i += blockDim.x)
            smw[WF_OFF + i] = p.W[8][i];
    }
    __syncthreads();

    const int row = blockIdx.x * blockDim.x + threadIdx.x;
    if (row >= p.B) return;

    // h buffer: final layout h[0..79] = [outs8, outs7, ..., outs1, x]
    // x lives at [72..79]; layer L writes outs at [63-9L .. 71-9L].
    // h[80..83] = 0 padding so padded (zero) weights multiply a defined value.
    float h[84];
    {
        const float4* xr = reinterpret_cast<const float4*>(p.x + (size_t)row * 8);
        float4 x0 = xr[0];
        float4 x1 = xr[1];
        h[72] = x0.x; h[73] = x0.y; h[74] = x0.z; h[75] = x0.w;
        h[76] = x1.x; h[77] = x1.y; h[78] = x1.z; h[79] = x1.w;
        h[80] = 0.0f; h[81] = 0.0f; h[82] = 0.0f; h[83] = 0.0f;
    }

    do_layer<0>(h, smw);
    do_layer<1>(h, smw);
    do_layer<2>(h, smw);
    do_layer<3>(h, smw);
    do_layer<4>(h, smw);
    do_layer<5>(h, smw);
    do_layer<6>(h, smw);
    do_layer<7>(h, smw);

    // final: out = dot(Wf, h[0..79])
    float acc = 0.0f;
#pragma unroll
    for (int k = 0; k < 80; k += 4) {
        float4 w = *reinterpret_cast<const float4*>(smw + WF_OFF + k);
        acc = fmaf(w.x, h[k + 0], acc);
        acc = fmaf(w.y, h[k + 1], acc);
        acc = fmaf(w.z, h[k + 2], acc);
        acc = fmaf(w.w, h[k + 3], acc);
    }
    p.out[row] = acc;
}

extern "C" void kernel_launch(void* const* d_in, const int* in_sizes, int n_in,
                              void* d_out, int out_size) {
    NetParams p;
    p.x = (const float*)d_in[0];
    for (int i = 0; i < 9; ++i) p.W[i] = (const float*)d_in[1 + i];
    p.out = (float*)d_out;
    p.B   = in_sizes[0] / 8;

    const int threads = 256;
    const int blocks  = (p.B + threads - 1) / threads;
    netnew_kernel<<<blocks, threads>>>(p);
}